// round 7
// baseline (speedup 1.0000x reference)
#include <cuda_runtime.h>
#include <cuda_fp16.h>
#include <cstdint>

// ---------------------------------------------------------------------------
// Problem constants
// ---------------------------------------------------------------------------
#define SIG_LEN     262144
#define NFFT        1024
#define HOP         256
#define PADV        512
#define BATCH       16
#define F_BINS      513
#define N_FRAMES    1025
#define KF2         256            // twice-folded K

// GEMM tiling: CTA = 64(t) x 128(g), dual GEMM (real+imag)
#define BM 64
#define BN 128
#define BK 32
#define KITERS (KF2 / BK)          // 8
#define STAGES 3

#define AB_STRIDE 40               // halves per smem row (32 + 8 pad)
// stage rows: AR[0..63] AI[64..127] KC[128..255] KS[256..383]
#define STAGE_ROWS  384
#define STAGE_BYTES (STAGE_ROWS * AB_STRIDE * 2)   // 30720
#define SMEM_TOTAL  (STAGES * STAGE_BYTES)         // 92160

// fold kernel staging
#define FOLD_FRAMES 32
#define FOLD_SPAN   (FOLD_FRAMES * HOP + NFFT)     // 9216 floats

// ---------------------------------------------------------------------------
// Device scratch.  Classes: 0=RE (real,even f), 1=RO (real,odd), 2=IE, 3=IO
// ---------------------------------------------------------------------------
__device__ __half g_A[4][BATCH * N_FRAMES * KF2];  // frames per class [b][t][s]
__device__ __half g_K[4][KF2 * KF2];               // kernels per class [g][s]
__device__ float  g_E512[BATCH * N_FRAMES];        // y[512] per (b,t)

// ---------------------------------------------------------------------------
// PTX helpers (sm_100-safe)
// ---------------------------------------------------------------------------
__device__ __forceinline__ uint32_t smem_to_u32(const void* p) {
    uint32_t a;
    asm("{ .reg .u64 t; cvta.to.shared.u64 t, %1; cvt.u32.u64 %0, t; }"
        : "=r"(a) : "l"(p));
    return a;
}
__device__ __forceinline__ void cp_async16(uint32_t dst, const void* src) {
    asm volatile("cp.async.cg.shared.global [%0], [%1], 16;" :: "r"(dst), "l"(src));
}
#define CP_COMMIT() asm volatile("cp.async.commit_group;" ::: "memory")
#define CP_WAIT(N)  asm volatile("cp.async.wait_group %0;" :: "n"(N) : "memory")

__device__ __forceinline__ void ldmatrix_x4(uint32_t* r, uint32_t addr) {
    asm volatile("ldmatrix.sync.aligned.m8n8.x4.shared.b16 {%0,%1,%2,%3}, [%4];"
                 : "=r"(r[0]), "=r"(r[1]), "=r"(r[2]), "=r"(r[3]) : "r"(addr));
}
__device__ __forceinline__ void mma_16816(float* c, const uint32_t* a,
                                          uint32_t b0, uint32_t b1) {
    asm volatile(
        "mma.sync.aligned.m16n8k16.row.col.f32.f16.f16.f32 "
        "{%0,%1,%2,%3}, {%4,%5,%6,%7}, {%8,%9}, {%0,%1,%2,%3};"
        : "+f"(c[0]), "+f"(c[1]), "+f"(c[2]), "+f"(c[3])
        : "r"(a[0]), "r"(a[1]), "r"(a[2]), "r"(a[3]), "r"(b0), "r"(b1));
}

__device__ __forceinline__ int reflect_idx(int j) {   // padded coord -> signal idx
    int idx = j - PADV;
    idx = (idx < 0) ? -idx : idx;
    idx = (idx >= SIG_LEN) ? (2 * SIG_LEN - 2 - idx) : idx;
    return idx;
}

// ---------------------------------------------------------------------------
// Fused prologue.
//   blockIdx.x < 33 : fold frames (32 per block; chunk 32 = frame 1024 only)
//   blockIdx.x == 33: build analytic kernel matrices (16 y-slices)
//
// Fold math (validated round 5):
//   y[k] = x[k]*w[k];  E[j]=y[j]+y[1024-j], O[j]=y[j]-y[1024-j]; E[512]=y[512]
//   slot s (j=s+1, s<255): RE=E[j]+E[512-j], RO=E[j]-E[512-j],
//                          IE=O[j]-O[512-j], IO=O[j]+O[512-j]
//   slot 255: RE=E[256], RO=E[512], IE=0, IO=O[256]
// Kernel matrices (g,s; j=s+1):
//   K0=cos(pi g j/256), K1=cos(pi(2g+1)j/512) [slot255=-1],
//   K2=-sin(pi g j/256), K3=-sin(pi(2g+1)j/512)
// ---------------------------------------------------------------------------
__global__ void __launch_bounds__(256) fold_kernel(const float* __restrict__ sig) {
    if (blockIdx.x == 33) {            // kernel-matrix builder slice
        const int i0 = blockIdx.y * 4096 + threadIdx.x * 16;
        #pragma unroll
        for (int v = 0; v < 16; ++v) {
            const int i = i0 + v;
            const int g = i >> 8, ss = i & 255;
            const float j = (float)(ss + 1);
            const float ge = (float)g * j * (1.0f / 256.0f);
            const float go = (float)(2 * g + 1) * j * (1.0f / 512.0f);
            g_K[0][i] = __float2half(cospif(ge));
            g_K[1][i] = __float2half((ss < 255) ? cospif(go) : -1.0f);
            g_K[2][i] = __float2half(-sinpif(ge));
            g_K[3][i] = __float2half(-sinpif(go));
        }
        return;
    }

    __shared__ float s[FOLD_SPAN];
    __shared__ float wv[257];
    const int tid = threadIdx.x;
    const int b = blockIdx.y;
    const int t0 = blockIdx.x * FOLD_FRAMES;
    const int base = t0 * HOP;
    const float* sg = sig + (size_t)b * SIG_LEN;

    #pragma unroll 4
    for (int i = tid; i < FOLD_SPAN; i += 256)
        s[i] = sg[reflect_idx(base + i)];
    for (int i = tid; i <= 256; i += 256)
        wv[i] = 0.5f - 0.5f * cospif((float)i / 512.0f);
    __syncthreads();

    const int warp = tid >> 5, lane = tid & 31;
    const int nfr = (t0 == 1024) ? 1 : FOLD_FRAMES;
    for (int lt = warp; lt < nfr; lt += 8) {
        const int t = t0 + lt;
        const float* sf = s + lt * HOP;
        const size_t ro = ((size_t)b * N_FRAMES + t) * KF2;
        __half2* RE = reinterpret_cast<__half2*>(g_A[0] + ro);
        __half2* RO = reinterpret_cast<__half2*>(g_A[1] + ro);
        __half2* IE = reinterpret_cast<__half2*>(g_A[2] + ro);
        __half2* IO = reinterpret_cast<__half2*>(g_A[3] + ro);
        if (lane == 0)
            g_E512[b * N_FRAMES + t] = sf[512];   // w[512] = 1
        #pragma unroll
        for (int qq = 0; qq < 4; ++qq) {
            const int m = lane + qq * 32;          // half2 index: slots 2m, 2m+1
            float re[2], rr[2], ie[2], io[2];
            #pragma unroll
            for (int u = 0; u < 2; ++u) {
                const int ss = 2 * m + u;
                const int j = ss + 1;              // 1..256
                const float wj = wv[j];
                const float wc = 1.0f - wj;
                const float yj  = sf[j]        * wj;
                const float ymj = sf[1024 - j] * wj;
                const float ya  = sf[512 - j]  * wc;
                const float yb  = sf[512 + j]  * wc;
                const float uu = yj + ymj, vv = yj - ymj;
                const float pp = ya + yb,  q2 = ya - yb;
                re[u] = uu + pp;  rr[u] = uu - pp;
                ie[u] = vv - q2;  io[u] = vv + q2;
                if (ss == 255) {
                    re[u] = uu;                    // E[256]
                    rr[u] = sf[512];               // E[512]
                    io[u] = vv;                    // O[256]
                    ie[u] = 0.f;
                }
            }
            RE[m] = __floats2half2_rn(re[0], re[1]);
            RO[m] = __floats2half2_rn(rr[0], rr[1]);
            IE[m] = __floats2half2_rn(ie[0], ie[1]);
            IO[m] = __floats2half2_rn(io[0], io[1]);
        }
    }
}

// ---------------------------------------------------------------------------
// Merged edge kernel.
//   blockIdx.x < 1026  : frame t=1024, one warp per (b,f), f=0..512
//   blockIdx.x >= 1026 : bin f=512, t<1024, one warp per (b,t)
// ---------------------------------------------------------------------------
__global__ void __launch_bounds__(256) edge_kernel(float* __restrict__ out) {
    const int lane = threadIdx.x & 31;
    if (blockIdx.x < 1026) {
        const int gw = blockIdx.x * 8 + (threadIdx.x >> 5);
        if (gw >= BATCH * F_BINS) return;
        const int b = gw / F_BINS, f = gw - b * F_BINS;
        const size_t ro = ((size_t)b * N_FRAMES + 1024) * KF2;
        float ar = 0.f, ai = 0.f;
        if (f == 512) {
            const __half2* A = reinterpret_cast<const __half2*>(g_A[0] + ro);
            #pragma unroll
            for (int q = 0; q < 4; ++q) {
                float2 a = __half22float2(A[lane + q * 32]);
                ar += a.y - a.x;                 // sign (-1)^(s+1)
            }
        } else {
            const int p = f & 1, g = f >> 1;
            const __half2* Ar = reinterpret_cast<const __half2*>(g_A[p] + ro);
            const __half2* Kr = reinterpret_cast<const __half2*>(g_K[p] + (size_t)g * KF2);
            const __half2* Ai = reinterpret_cast<const __half2*>(g_A[2 + p] + ro);
            const __half2* Ki = reinterpret_cast<const __half2*>(g_K[2 + p] + (size_t)g * KF2);
            #pragma unroll
            for (int q = 0; q < 4; ++q) {
                const int m = lane + q * 32;
                float2 a = __half22float2(Ar[m]), k = __half22float2(Kr[m]);
                float2 c = __half22float2(Ai[m]), d = __half22float2(Ki[m]);
                ar += a.x * k.x + a.y * k.y;
                ai += c.x * d.x + c.y * d.y;
            }
        }
        #pragma unroll
        for (int off = 16; off; off >>= 1) {
            ar += __shfl_xor_sync(0xffffffffu, ar, off);
            ai += __shfl_xor_sync(0xffffffffu, ai, off);
        }
        if (lane == 0) {
            if ((f & 1) == 0) ar += g_E512[b * N_FRAMES + 1024];
            if (f == 512) ai = 0.f;
            float* op = out + (((size_t)b * F_BINS + f) * N_FRAMES + 1024) * 2;
            op[0] = ar;
            op[1] = ai;
        }
    } else {
        const int gw = (blockIdx.x - 1026) * 8 + (threadIdx.x >> 5);
        if (gw >= BATCH * 1024) return;
        const int b = gw >> 10, t = gw & 1023;
        const __half2* A = reinterpret_cast<const __half2*>(
            g_A[0] + ((size_t)b * N_FRAMES + t) * KF2);
        float ar = 0.f;
        #pragma unroll
        for (int q = 0; q < 4; ++q) {
            float2 a = __half22float2(A[lane + q * 32]);
            ar += a.y - a.x;
        }
        #pragma unroll
        for (int off = 16; off; off >>= 1)
            ar += __shfl_xor_sync(0xffffffffu, ar, off);
        if (lane == 0) {
            float* op = out + (((size_t)b * F_BINS + 512) * N_FRAMES + t) * 2;
            op[0] = ar + g_E512[b * N_FRAMES + t];
            op[1] = 0.f;
        }
    }
}

// ---------------------------------------------------------------------------
// Main GEMM: dual (real+imag) per CTA for one parity p.
//   real[t][g] = sum_s A[p][t][s]   * K[p][g][s]
//   imag[t][g] = sum_s A[2+p][t][s] * K[2+p][g][s]
//   f = 2g + p; out[b][f][t] = {real (+E512 if p==0), imag}  (float2 store)
//   grid = (2 g-tiles, 16 t-tiles, 32 = p*16+b), block = 256 (2x4 warps)
//   warp tile 32(t) x 32(g) per GEMM
// ---------------------------------------------------------------------------
__global__ void __launch_bounds__(256, 2) stft_gemm(float* __restrict__ out) {
    extern __shared__ __half smem[];
    const uint32_t sb = smem_to_u32(smem);
    const int tid = threadIdx.x;
    const int wid = tid >> 5;
    const int lane = tid & 31;
    const int n0 = blockIdx.x * BN;           // g-range start
    const int m0 = blockIdx.y * BM;           // t-range start
    const int b  = blockIdx.z & 15;
    const int p  = blockIdx.z >> 4;           // parity

    const __half* pAR = g_A[p]     + (size_t)b * N_FRAMES * KF2;
    const __half* pAI = g_A[2 + p] + (size_t)b * N_FRAMES * KF2;
    const __half* pKC = g_K[p];
    const __half* pKS = g_K[2 + p];

    // cp.async: 1536 16B-chunks per stage, 6 per thread; fixed (row, col)
    const __half* srcb[6];
    uint32_t dsto[6];
    #pragma unroll
    for (int k = 0; k < 6; ++k) {
        const int q = tid + k * 256;
        const int r = q >> 2, c = q & 3;
        dsto[k] = (r * AB_STRIDE + c * 8) * 2;
        const __half* bp;
        if      (r < 64)  bp = pAR + (size_t)(m0 + r) * KF2;
        else if (r < 128) bp = pAI + (size_t)(m0 + r - 64) * KF2;
        else if (r < 256) bp = pKC + (size_t)(n0 + r - 128) * KF2;
        else              bp = pKS + (size_t)(n0 + r - 256) * KF2;
        srcb[k] = bp + c * 8;
    }

    const int lm   = lane >> 3;
    const int l7   = lane & 7;
    const int row8 = (lm & 1) * 8 + l7;
    const int off8 = (lm >> 1) * 8;

    const int warp_m = wid & 1;               // 2 warps over t (32 each)
    const int warp_n = wid >> 1;              // 4 warps over g (32 each)

    float accR[2][4][4], accI[2][4][4];
    #pragma unroll
    for (int i = 0; i < 2; ++i)
        #pragma unroll
        for (int j = 0; j < 4; ++j)
            #pragma unroll
            for (int v = 0; v < 4; ++v) { accR[i][j][v] = 0.f; accI[i][j][v] = 0.f; }

    auto load_stage = [&](int s, int k0) {
        const uint32_t d = sb + s * STAGE_BYTES;
        #pragma unroll
        for (int k = 0; k < 6; ++k)
            cp_async16(d + dsto[k], srcb[k] + k0);
    };

    load_stage(0, 0);  CP_COMMIT();
    load_stage(1, BK); CP_COMMIT();

    int s = 0, ps = 2;
    for (int i = 0; i < KITERS; ++i) {
        CP_WAIT(STAGES - 2);
        __syncthreads();

        const uint32_t st = sb + s * STAGE_BYTES;

        #pragma unroll
        for (int ks = 0; ks < BK; ks += 16) {
            uint32_t AR[2][4], AI[2][4];
            #pragma unroll
            for (int mf = 0; mf < 2; ++mf) {
                const int row = warp_m * 32 + mf * 16 + row8;
                ldmatrix_x4(AR[mf], st + (row * AB_STRIDE + ks + off8) * 2);
                ldmatrix_x4(AI[mf], st + ((row + 64) * AB_STRIDE + ks + off8) * 2);
            }
            uint32_t BC[4][2], BS[4][2];
            #pragma unroll
            for (int ph = 0; ph < 2; ++ph) {
                const int nrow = warp_n * 32 + ph * 16 + row8;
                uint32_t r[4];
                ldmatrix_x4(r, st + ((nrow + 128) * AB_STRIDE + ks + off8) * 2);
                BC[2 * ph][0]     = r[0]; BC[2 * ph][1]     = r[2];
                BC[2 * ph + 1][0] = r[1]; BC[2 * ph + 1][1] = r[3];
                ldmatrix_x4(r, st + ((nrow + 256) * AB_STRIDE + ks + off8) * 2);
                BS[2 * ph][0]     = r[0]; BS[2 * ph][1]     = r[2];
                BS[2 * ph + 1][0] = r[1]; BS[2 * ph + 1][1] = r[3];
            }
            #pragma unroll
            for (int mf = 0; mf < 2; ++mf)
                #pragma unroll
                for (int nf = 0; nf < 4; ++nf) {
                    mma_16816(accR[mf][nf], AR[mf], BC[nf][0], BC[nf][1]);
                    mma_16816(accI[mf][nf], AI[mf], BS[nf][0], BS[nf][1]);
                }
        }

        if (i + 2 < KITERS)
            load_stage(ps, (i + 2) * BK);
        CP_COMMIT();
        s  = (s  == 2) ? 0 : s + 1;
        ps = (ps == 2) ? 0 : ps + 1;
    }

    // epilogue: float2 {real, imag} at out[b][f=2g+p][t]
    const int t_base = m0 + warp_m * 32 + (lane >> 2);
    const int g_base = n0 + warp_n * 32 + 2 * (lane & 3);
    const float* e512 = g_E512 + (size_t)b * N_FRAMES;
    float2* ob = reinterpret_cast<float2*>(out) + (size_t)b * F_BINS * N_FRAMES;

    #pragma unroll
    for (int mf = 0; mf < 2; ++mf) {
        const int t0 = t_base + mf * 16;
        const float a0 = (p == 0) ? e512[t0]     : 0.f;
        const float a1 = (p == 0) ? e512[t0 + 8] : 0.f;
        #pragma unroll
        for (int nf = 0; nf < 4; ++nf) {
            const int g0 = g_base + nf * 8;
            const int f0 = 2 * g0 + p;
            const int f1 = f0 + 2;
            float2* p0 = ob + (size_t)f0 * N_FRAMES + t0;
            float2* p1 = ob + (size_t)f1 * N_FRAMES + t0;
            p0[0] = make_float2(accR[mf][nf][0] + a0, accI[mf][nf][0]);
            p1[0] = make_float2(accR[mf][nf][1] + a0, accI[mf][nf][1]);
            p0[8] = make_float2(accR[mf][nf][2] + a1, accI[mf][nf][2]);
            p1[8] = make_float2(accR[mf][nf][3] + a1, accI[mf][nf][3]);
        }
    }
}

// ---------------------------------------------------------------------------
// Host launcher
// ---------------------------------------------------------------------------
extern "C" void kernel_launch(void* const* d_in, const int* in_sizes, int n_in,
                              void* d_out, int out_size) {
    (void)in_sizes; (void)n_in; (void)out_size;
    const float* signal = (const float*)d_in[0];   // [16, 262144] fp32
    float* out = (float*)d_out;                    // [16, 513, 1025, 2] fp32

    // Fused prologue: fold frames + build kernel matrices
    fold_kernel<<<dim3(34, BATCH), 256>>>(signal);

    // Main GEMMs: 2 parities x 16 batches, dual real/imag per CTA
    static bool attr_set = false;
    if (!attr_set) {
        cudaFuncSetAttribute(stft_gemm,
                             cudaFuncAttributeMaxDynamicSharedMemorySize,
                             SMEM_TOTAL);
        attr_set = true;
    }
    stft_gemm<<<dim3(2, 16, 32), 256, SMEM_TOTAL>>>(out);

    // Edges (t=1024 all f; f=512 t<1024) in one launch
    edge_kernel<<<1026 + 2048, 256>>>(out);
}

// round 9
// speedup vs baseline: 1.0496x; 1.0496x over previous
#include <cuda_runtime.h>
#include <cuda_fp16.h>
#include <cstdint>

// ---------------------------------------------------------------------------
// Problem constants
// ---------------------------------------------------------------------------
#define SIG_LEN     262144
#define NFFT        1024
#define HOP         256
#define PADV        512
#define BATCH       16
#define F_BINS      513
#define N_FRAMES    1025
#define KF2         256            // twice-folded K

// GEMM tiling: CTA = 64(t) x 128(g), dual GEMM (real+imag)
#define BM 64
#define BN 128
#define BK 32
#define KITERS (KF2 / BK)          // 8
#define STAGES 3

#define AB_STRIDE 40               // halves per smem row (32 + 8 pad)
// stage rows: AR[0..63] AI[64..127] KC[128..255] KS[256..383]
#define STAGE_ROWS  384
#define STAGE_BYTES (STAGE_ROWS * AB_STRIDE * 2)   // 30720
#define SMEM_TOTAL  (STAGES * STAGE_BYTES)         // 92160

// fold grid: warp per (b,t); 8 warps/block
#define FOLD_BLOCKS ((BATCH * N_FRAMES + 7) / 8)   // 2050
#define KBUILD_BLOCKS 16

// ---------------------------------------------------------------------------
// Device scratch.  Classes: 0=RE (real,even f), 1=RO (real,odd), 2=IE, 3=IO
// ---------------------------------------------------------------------------
__device__ __half g_A[4][BATCH * N_FRAMES * KF2];  // frames per class [b][t][s]
__device__ __half g_K[4][KF2 * KF2];               // kernels per class [g][s]
__device__ float  g_E512[BATCH * N_FRAMES];        // y[512] per (b,t)

// ---------------------------------------------------------------------------
// PTX helpers (sm_100-safe)
// ---------------------------------------------------------------------------
__device__ __forceinline__ uint32_t smem_to_u32(const void* p) {
    uint32_t a;
    asm("{ .reg .u64 t; cvta.to.shared.u64 t, %1; cvt.u32.u64 %0, t; }"
        : "=r"(a) : "l"(p));
    return a;
}
__device__ __forceinline__ void cp_async16(uint32_t dst, const void* src) {
    asm volatile("cp.async.cg.shared.global [%0], [%1], 16;" :: "r"(dst), "l"(src));
}
#define CP_COMMIT() asm volatile("cp.async.commit_group;" ::: "memory")
#define CP_WAIT(N)  asm volatile("cp.async.wait_group %0;" :: "n"(N) : "memory")

__device__ __forceinline__ void ldmatrix_x4(uint32_t* r, uint32_t addr) {
    asm volatile("ldmatrix.sync.aligned.m8n8.x4.shared.b16 {%0,%1,%2,%3}, [%4];"
                 : "=r"(r[0]), "=r"(r[1]), "=r"(r[2]), "=r"(r[3]) : "r"(addr));
}
__device__ __forceinline__ void mma_16816(float* c, const uint32_t* a,
                                          uint32_t b0, uint32_t b1) {
    asm volatile(
        "mma.sync.aligned.m16n8k16.row.col.f32.f16.f16.f32 "
        "{%0,%1,%2,%3}, {%4,%5,%6,%7}, {%8,%9}, {%0,%1,%2,%3};"
        : "+f"(c[0]), "+f"(c[1]), "+f"(c[2]), "+f"(c[3])
        : "r"(a[0]), "r"(a[1]), "r"(a[2]), "r"(a[3]), "r"(b0), "r"(b1));
}

__device__ __forceinline__ int reflect_idx(int j) {   // padded coord -> signal idx
    int idx = j - PADV;
    idx = (idx < 0) ? -idx : idx;
    idx = (idx >= SIG_LEN) ? (2 * SIG_LEN - 2 - idx) : idx;
    return idx;
}

// ---------------------------------------------------------------------------
// Fold body (math validated rounds 5-7).
//   y[k] = x[k]*w[k];  E[j]=y[j]+y[1024-j], O[j]=y[j]-y[1024-j]; E[512]=y[512]
//   slot s (j=s+1, s<255): RE=E[j]+E[512-j], RO=E[j]-E[512-j],
//                          IE=O[j]-O[512-j], IO=O[j]+O[512-j]
//   slot 255: RE=E[256], RO=E[512], IE=0, IO=O[256]
//
//   REFLECT=false: wp = window base pointer (sig + t*HOP - PADV), direct loads
//   REFLECT=true : wp = batch signal base, poff = t*HOP, reflect per access
// ---------------------------------------------------------------------------
template <bool REFLECT>
__device__ __forceinline__ void fold_body(const float* __restrict__ wp, int poff,
                                          int lane, size_t ro, int e_idx) {
    __half2* RE = reinterpret_cast<__half2*>(g_A[0] + ro);
    __half2* RO = reinterpret_cast<__half2*>(g_A[1] + ro);
    __half2* IE = reinterpret_cast<__half2*>(g_A[2] + ro);
    __half2* IO = reinterpret_cast<__half2*>(g_A[3] + ro);

    #define XLD(k) (REFLECT ? wp[reflect_idx(poff + (k))] : __ldg(wp + (k)))

    const float x512 = XLD(512);
    if (lane == 0) g_E512[e_idx] = x512;         // w[512] = 1
    #pragma unroll
    for (int qq = 0; qq < 4; ++qq) {
        const int m = lane + qq * 32;            // half2 index: slots 2m, 2m+1
        float re[2], rr[2], ie[2], io[2];
        #pragma unroll
        for (int u = 0; u < 2; ++u) {
            const int ss = 2 * m + u;
            const int j = ss + 1;                // 1..256
            const float xj  = XLD(j);
            const float xmj = XLD(1024 - j);
            const float xa  = XLD(512 - j);
            const float xb  = XLD(512 + j);
            const float wj = 0.5f - 0.5f * cospif((float)j * (1.0f / 512.0f));
            const float wc = 1.0f - wj;
            const float yj  = xj  * wj;
            const float ymj = xmj * wj;
            const float ya  = xa  * wc;
            const float yb  = xb  * wc;
            const float uu = yj + ymj, vv = yj - ymj;
            const float pp = ya + yb,  q2 = ya - yb;
            re[u] = uu + pp;  rr[u] = uu - pp;
            ie[u] = vv - q2;  io[u] = vv + q2;
            if (ss == 255) {
                re[u] = uu;                      // E[256]
                rr[u] = x512;                    // E[512]
                io[u] = vv;                      // O[256]
                ie[u] = 0.f;
            }
        }
        RE[m] = __floats2half2_rn(re[0], re[1]);
        RO[m] = __floats2half2_rn(rr[0], rr[1]);
        IE[m] = __floats2half2_rn(ie[0], ie[1]);
        IO[m] = __floats2half2_rn(io[0], io[1]);
    }
    #undef XLD
}

// ---------------------------------------------------------------------------
// Fused prologue: warp-per-frame fold (no smem) + kernel-matrix builder tail.
//   blockIdx.x <  FOLD_BLOCKS           : 8 frames per block
//   blockIdx.x >= FOLD_BLOCKS (16 blks) : analytic kernel matrices
// ---------------------------------------------------------------------------
__global__ void __launch_bounds__(256) fold_kernel(const float* __restrict__ sig) {
    if (blockIdx.x >= FOLD_BLOCKS) {            // kernel-matrix builder
        const int i0 = (blockIdx.x - FOLD_BLOCKS) * 4096 + threadIdx.x * 16;
        #pragma unroll
        for (int v = 0; v < 16; ++v) {
            const int i = i0 + v;
            const int g = i >> 8, ss = i & 255;
            const float j = (float)(ss + 1);
            const float ge = (float)g * j * (1.0f / 256.0f);
            const float go = (float)(2 * g + 1) * j * (1.0f / 512.0f);
            g_K[0][i] = __float2half(cospif(ge));
            g_K[1][i] = __float2half((ss < 255) ? cospif(go) : -1.0f);
            g_K[2][i] = __float2half(-sinpif(ge));
            g_K[3][i] = __float2half(-sinpif(go));
        }
        return;
    }

    const int gw = blockIdx.x * 8 + (threadIdx.x >> 5);
    if (gw >= BATCH * N_FRAMES) return;
    const int lane = threadIdx.x & 31;
    const int b = gw / N_FRAMES;
    const int t = gw - b * N_FRAMES;
    const float* sg = sig + (size_t)b * SIG_LEN;
    const size_t ro = (size_t)gw * KF2;          // gw == b*N_FRAMES+t
    const int p = t * HOP;

    if (t >= 2 && t <= 1021) {                   // reflect-free fast path
        fold_body<false>(sg + (p - PADV), 0, lane, ro, gw);
    } else {                                     // edge frames (80 warps)
        fold_body<true>(sg, p, lane, ro, gw);
    }
}

// ---------------------------------------------------------------------------
// Merged edge kernel.
//   blockIdx.x < 1026  : frame t=1024, one warp per (b,f), f=0..512
//   blockIdx.x >= 1026 : bin f=512, t<1024, one warp per (b,t)
// ---------------------------------------------------------------------------
__global__ void __launch_bounds__(256) edge_kernel(float* __restrict__ out) {
    const int lane = threadIdx.x & 31;
    if (blockIdx.x < 1026) {
        const int gw = blockIdx.x * 8 + (threadIdx.x >> 5);
        if (gw >= BATCH * F_BINS) return;
        const int b = gw / F_BINS, f = gw - b * F_BINS;
        const size_t ro = ((size_t)b * N_FRAMES + 1024) * KF2;
        float ar = 0.f, ai = 0.f;
        if (f == 512) {
            const __half2* A = reinterpret_cast<const __half2*>(g_A[0] + ro);
            #pragma unroll
            for (int q = 0; q < 4; ++q) {
                float2 a = __half22float2(A[lane + q * 32]);
                ar += a.y - a.x;                 // sign (-1)^(s+1)
            }
        } else {
            const int p = f & 1, g = f >> 1;
            const __half2* Ar = reinterpret_cast<const __half2*>(g_A[p] + ro);
            const __half2* Kr = reinterpret_cast<const __half2*>(g_K[p] + (size_t)g * KF2);
            const __half2* Ai = reinterpret_cast<const __half2*>(g_A[2 + p] + ro);
            const __half2* Ki = reinterpret_cast<const __half2*>(g_K[2 + p] + (size_t)g * KF2);
            #pragma unroll
            for (int q = 0; q < 4; ++q) {
                const int m = lane + q * 32;
                float2 a = __half22float2(Ar[m]), k = __half22float2(Kr[m]);
                float2 c = __half22float2(Ai[m]), d = __half22float2(Ki[m]);
                ar += a.x * k.x + a.y * k.y;
                ai += c.x * d.x + c.y * d.y;
            }
        }
        #pragma unroll
        for (int off = 16; off; off >>= 1) {
            ar += __shfl_xor_sync(0xffffffffu, ar, off);
            ai += __shfl_xor_sync(0xffffffffu, ai, off);
        }
        if (lane == 0) {
            if ((f & 1) == 0) ar += g_E512[b * N_FRAMES + 1024];
            if (f == 512) ai = 0.f;
            float* op = out + (((size_t)b * F_BINS + f) * N_FRAMES + 1024) * 2;
            op[0] = ar;
            op[1] = ai;
        }
    } else {
        const int gw = (blockIdx.x - 1026) * 8 + (threadIdx.x >> 5);
        if (gw >= BATCH * 1024) return;
        const int b = gw >> 10, t = gw & 1023;
        const __half2* A = reinterpret_cast<const __half2*>(
            g_A[0] + ((size_t)b * N_FRAMES + t) * KF2);
        float ar = 0.f;
        #pragma unroll
        for (int q = 0; q < 4; ++q) {
            float2 a = __half22float2(A[lane + q * 32]);
            ar += a.y - a.x;
        }
        #pragma unroll
        for (int off = 16; off; off >>= 1)
            ar += __shfl_xor_sync(0xffffffffu, ar, off);
        if (lane == 0) {
            float* op = out + (((size_t)b * F_BINS + 512) * N_FRAMES + t) * 2;
            op[0] = ar + g_E512[b * N_FRAMES + t];
            op[1] = 0.f;
        }
    }
}

// ---------------------------------------------------------------------------
// Main GEMM: dual (real+imag) per CTA for one parity p.
//   real[t][g] = sum_s A[p][t][s]   * K[p][g][s]
//   imag[t][g] = sum_s A[2+p][t][s] * K[2+p][g][s]
//   f = 2g + p; out[b][f][t] = {real (+E512 if p==0), imag}  (float2 store)
//   grid = (2 g-tiles, 16 t-tiles, 32 = p*16+b), block = 256 (2x4 warps)
// ---------------------------------------------------------------------------
__global__ void __launch_bounds__(256, 2) stft_gemm(float* __restrict__ out) {
    extern __shared__ __half smem[];
    const uint32_t sb = smem_to_u32(smem);
    const int tid = threadIdx.x;
    const int wid = tid >> 5;
    const int lane = tid & 31;
    const int n0 = blockIdx.x * BN;           // g-range start
    const int m0 = blockIdx.y * BM;           // t-range start
    const int b  = blockIdx.z & 15;
    const int p  = blockIdx.z >> 4;           // parity

    const __half* pAR = g_A[p]     + (size_t)b * N_FRAMES * KF2;
    const __half* pAI = g_A[2 + p] + (size_t)b * N_FRAMES * KF2;
    const __half* pKC = g_K[p];
    const __half* pKS = g_K[2 + p];

    // cp.async: 1536 16B-chunks per stage, 6 per thread; fixed (row, col)
    const __half* srcb[6];
    uint32_t dsto[6];
    #pragma unroll
    for (int k = 0; k < 6; ++k) {
        const int q = tid + k * 256;
        const int r = q >> 2, c = q & 3;
        dsto[k] = (r * AB_STRIDE + c * 8) * 2;
        const __half* bp;
        if      (r < 64)  bp = pAR + (size_t)(m0 + r) * KF2;
        else if (r < 128) bp = pAI + (size_t)(m0 + r - 64) * KF2;
        else if (r < 256) bp = pKC + (size_t)(n0 + r - 128) * KF2;
        else              bp = pKS + (size_t)(n0 + r - 256) * KF2;
        srcb[k] = bp + c * 8;
    }

    const int lm   = lane >> 3;
    const int l7   = lane & 7;
    const int row8 = (lm & 1) * 8 + l7;
    const int off8 = (lm >> 1) * 8;

    const int warp_m = wid & 1;               // 2 warps over t (32 each)
    const int warp_n = wid >> 1;              // 4 warps over g (32 each)

    float accR[2][4][4], accI[2][4][4];
    #pragma unroll
    for (int i = 0; i < 2; ++i)
        #pragma unroll
        for (int j = 0; j < 4; ++j)
            #pragma unroll
            for (int v = 0; v < 4; ++v) { accR[i][j][v] = 0.f; accI[i][j][v] = 0.f; }

    auto load_stage = [&](int s, int k0) {
        const uint32_t d = sb + s * STAGE_BYTES;
        #pragma unroll
        for (int k = 0; k < 6; ++k)
            cp_async16(d + dsto[k], srcb[k] + k0);
    };

    load_stage(0, 0);  CP_COMMIT();
    load_stage(1, BK); CP_COMMIT();

    int s = 0, ps = 2;
    for (int i = 0; i < KITERS; ++i) {
        CP_WAIT(STAGES - 2);
        __syncthreads();

        const uint32_t st = sb + s * STAGE_BYTES;

        #pragma unroll
        for (int ks = 0; ks < BK; ks += 16) {
            uint32_t AR[2][4], AI[2][4];
            #pragma unroll
            for (int mf = 0; mf < 2; ++mf) {
                const int row = warp_m * 32 + mf * 16 + row8;
                ldmatrix_x4(AR[mf], st + (row * AB_STRIDE + ks + off8) * 2);
                ldmatrix_x4(AI[mf], st + ((row + 64) * AB_STRIDE + ks + off8) * 2);
            }
            uint32_t BC[4][2], BS[4][2];
            #pragma unroll
            for (int ph = 0; ph < 2; ++ph) {
                const int nrow = warp_n * 32 + ph * 16 + row8;
                uint32_t r[4];
                ldmatrix_x4(r, st + ((nrow + 128) * AB_STRIDE + ks + off8) * 2);
                BC[2 * ph][0]     = r[0]; BC[2 * ph][1]     = r[2];
                BC[2 * ph + 1][0] = r[1]; BC[2 * ph + 1][1] = r[3];
                ldmatrix_x4(r, st + ((nrow + 256) * AB_STRIDE + ks + off8) * 2);
                BS[2 * ph][0]     = r[0]; BS[2 * ph][1]     = r[2];
                BS[2 * ph + 1][0] = r[1]; BS[2 * ph + 1][1] = r[3];
            }
            #pragma unroll
            for (int mf = 0; mf < 2; ++mf)
                #pragma unroll
                for (int nf = 0; nf < 4; ++nf) {
                    mma_16816(accR[mf][nf], AR[mf], BC[nf][0], BC[nf][1]);
                    mma_16816(accI[mf][nf], AI[mf], BS[nf][0], BS[nf][1]);
                }
        }

        if (i + 2 < KITERS)
            load_stage(ps, (i + 2) * BK);
        CP_COMMIT();
        s  = (s  == 2) ? 0 : s + 1;
        ps = (ps == 2) ? 0 : ps + 1;
    }

    // epilogue: float2 {real, imag} at out[b][f=2g+p][t]
    const int t_base = m0 + warp_m * 32 + (lane >> 2);
    const int g_base = n0 + warp_n * 32 + 2 * (lane & 3);
    const float* e512 = g_E512 + (size_t)b * N_FRAMES;
    float2* ob = reinterpret_cast<float2*>(out) + (size_t)b * F_BINS * N_FRAMES;

    #pragma unroll
    for (int mf = 0; mf < 2; ++mf) {
        const int t0 = t_base + mf * 16;
        const float a0 = (p == 0) ? e512[t0]     : 0.f;
        const float a1 = (p == 0) ? e512[t0 + 8] : 0.f;
        #pragma unroll
        for (int nf = 0; nf < 4; ++nf) {
            const int g0 = g_base + nf * 8;
            const int f0 = 2 * g0 + p;
            const int f1 = f0 + 2;
            float2* p0 = ob + (size_t)f0 * N_FRAMES + t0;
            float2* p1 = ob + (size_t)f1 * N_FRAMES + t0;
            p0[0] = make_float2(accR[mf][nf][0] + a0, accI[mf][nf][0]);
            p1[0] = make_float2(accR[mf][nf][1] + a0, accI[mf][nf][1]);
            p0[8] = make_float2(accR[mf][nf][2] + a1, accI[mf][nf][2]);
            p1[8] = make_float2(accR[mf][nf][3] + a1, accI[mf][nf][3]);
        }
    }
}

// ---------------------------------------------------------------------------
// Host launcher
// ---------------------------------------------------------------------------
extern "C" void kernel_launch(void* const* d_in, const int* in_sizes, int n_in,
                              void* d_out, int out_size) {
    (void)in_sizes; (void)n_in; (void)out_size;
    const float* signal = (const float*)d_in[0];   // [16, 262144] fp32
    float* out = (float*)d_out;                    // [16, 513, 1025, 2] fp32

    // Fused prologue: warp-per-frame fold + kernel matrices
    fold_kernel<<<FOLD_BLOCKS + KBUILD_BLOCKS, 256>>>(signal);

    // Main GEMMs: 2 parities x 16 batches, dual real/imag per CTA
    static bool attr_set = false;
    if (!attr_set) {
        cudaFuncSetAttribute(stft_gemm,
                             cudaFuncAttributeMaxDynamicSharedMemorySize,
                             SMEM_TOTAL);
        attr_set = true;
    }
    stft_gemm<<<dim3(2, 16, 32), 256, SMEM_TOTAL>>>(out);

    // Edges (t=1024 all f; f=512 t<1024) in one launch
    edge_kernel<<<1026 + 2048, 256>>>(out);
}